// round 1
// baseline (speedup 1.0000x reference)
#include <cuda_runtime.h>

#define BB     4
#define CC     32
#define HH     512
#define WW     512
#define NBOX   64
#define H_OUT_ 16
#define MAX_W_ 192

// One block per (b, n, i) output row. 192 threads = one per output column j.
// Weights computed once per (i, j), reused across all 32 channels.
__global__ __launch_bounds__(MAX_W_) void roirotate_kernel(
    const float* __restrict__ img,      // (B, C, H, W)
    const float* __restrict__ boxes,    // (B, N, 5)
    float* __restrict__ out,            // (B, N, C, H_OUT, MAX_W)
    float* __restrict__ maskf,          // (B, N, MAX_W) as float, or null
    unsigned char* __restrict__ masku8) // (B, N, MAX_W) as u8, or null
{
    const int bi = blockIdx.x;            // 0 .. B*N*H_OUT-1
    const int i  = bi & (H_OUT_ - 1);
    const int bn = bi >> 4;               // b*NBOX + n
    const int b  = bn >> 6;
    const int j  = threadIdx.x;

    const float* bx = boxes + bn * 5;
    const float left = bx[0];
    const float top  = bx[1];
    const float bw   = bx[2] - left;
    const float bh   = bx[3] - top;

    // width = int32(bw/bh * H_OUT): IEEE-correct division so truncation
    // matches the JAX reference bit-exactly (mask is binary!)
    const int   width  = (int)(__fdiv_rn(bw, bh) * (float)H_OUT_);
    const float each_w = __fdiv_rn(bw, (float)(width - 1));
    const float each_h = __fdiv_rn(bh, (float)(H_OUT_ - 1));

    const bool valid = (j < width);

    // out index: ((bn*C + c)*H_OUT + i)*MAX_W + j
    const long long obase = (long long)bn * CC * (H_OUT_ * MAX_W_)
                          + (long long)i * MAX_W_ + j;
    const long long cstride = (long long)(H_OUT_ * MAX_W_);

    if (i == 0) {
        if (maskf)  maskf [bn * MAX_W_ + j] = valid ? 1.0f : 0.0f;
        if (masku8) masku8[bn * MAX_W_ + j] = valid ? (unsigned char)1 : (unsigned char)0;
    }

    if (!valid) {
        // masked column: output is exactly 0 for every channel
        #pragma unroll
        for (int c = 0; c < CC; c++)
            out[obase + (long long)c * cstride] = 0.0f;
        return;
    }

    const float x = (float)j * each_w + left;
    const float y = (float)i * each_h + top;
    const float fx = floorf(x);
    const float fy = floorf(y);
    int x0 = (int)fx;
    int y0 = (int)fy;
    int x1 = x0 + 1;
    int y1 = y0 + 1;
    x0 = max(0, min(x0, WW - 1));
    x1 = max(0, min(x1, WW - 1));
    y0 = max(0, min(y0, HH - 1));
    y1 = max(0, min(y1, HH - 1));

    const float x0f = (float)x0, x1f = (float)x1;
    const float y0f = (float)y0, y1f = (float)y1;
    const float wa = (x1f - x) * (y1f - y);
    const float wb = (x1f - x) * (y - y0f);
    const float wc = (x - x0f) * (y1f - y);
    const float wd = (x - x0f) * (y - y0f);

    const int o00 = y0 * WW + x0;
    const int o10 = y1 * WW + x0;
    const int o01 = y0 * WW + x1;
    const int o11 = y1 * WW + x1;

    const float* ibase = img + (long long)b * CC * (HH * WW);

    #pragma unroll
    for (int c = 0; c < CC; c++) {
        const float* p = ibase + (long long)c * (HH * WW);
        const float ia = __ldg(p + o00);
        const float ib = __ldg(p + o10);
        const float ic = __ldg(p + o01);
        const float id = __ldg(p + o11);
        out[obase + (long long)c * cstride] = ia * wa + ib * wb + ic * wc + id * wd;
    }
}

extern "C" void kernel_launch(void* const* d_in, const int* in_sizes, int n_in,
                              void* d_out, int out_size)
{
    const float* img   = (const float*)d_in[0];
    const float* boxes = (const float*)d_in[1];

    const long long R = (long long)BB * NBOX * CC * H_OUT_ * MAX_W_; // 25,165,824
    const long long M = (long long)BB * NBOX * MAX_W_;               // 49,152

    const dim3 grid(BB * NBOX * H_OUT_);  // 4096 blocks
    const dim3 block(MAX_W_);             // 192 threads

    if ((long long)out_size == R * 4 + M) {
        // byte-packed tuple: raw fp32 result bytes then u8 mask
        unsigned char* ob = (unsigned char*)d_out;
        roirotate_kernel<<<grid, block>>>(img, boxes, (float*)ob, nullptr, ob + R * 4);
    } else if ((long long)out_size >= R + M) {
        // fp32-packed tuple: result then mask cast to fp32
        float* of = (float*)d_out;
        roirotate_kernel<<<grid, block>>>(img, boxes, of, of + R, nullptr);
    } else {
        // result only
        float* of = (float*)d_out;
        roirotate_kernel<<<grid, block>>>(img, boxes, of, nullptr, nullptr);
    }
}